// round 3
// baseline (speedup 1.0000x reference)
#include <cuda_runtime.h>

#define NN      61440        // nodes = 2048*30
#define EE      245760       // edges = 4*NN
#define BB      2048         // graphs
#define NATOMS  30
#define FL      64           // FEATURE_LEN
#define DD      256          // DIM_ATOM == DIM_GRAPH
#define SSIDE   2            // S
#define KNEI    32

// ---------------- device scratch (no runtime allocation allowed) ------------
__device__ float g_norm_src[NN];
__device__ float g_norm_dst[NN];
__device__ float g_agg1[NN * FL];
__device__ float g_h1[NN * DD];
__device__ float g_agg2[NN * DD];
__device__ float g_h2[NN * DD];
__device__ float g_item[SSIDE * BB * DD];
__device__ float g_target[BB * DD];
__device__ float g_react[BB * DD];
__device__ float g_normsum;

// ---------------- zero accumulators (runs every launch; graph-replayable) ---
__global__ void k_zero_all() {
    int t = blockIdx.x * blockDim.x + threadIdx.x;   // 15360*256 = 3,932,160
    float4 z = make_float4(0.f, 0.f, 0.f, 0.f);
    ((float4*)g_agg2)[t] = z;                         // NN*DD/4 = 3,932,160 exactly
    if (t < NN * FL / 4) ((float4*)g_agg1)[t] = z;
    if (t < NN / 4) {
        ((float4*)g_norm_src)[t] = z;
        ((float4*)g_norm_dst)[t] = z;
    }
    if (t < BB * DD / 4) ((float4*)g_react)[t] = z;
    if (t == 0) g_normsum = 0.f;
}

// ---------------- degrees + symmetric norm ---------------------------------
__global__ void k_deg(const int* __restrict__ src, const int* __restrict__ dst) {
    int e = blockIdx.x * blockDim.x + threadIdx.x;
    if (e < EE) {
        atomicAdd(&g_norm_src[__ldg(&src[e])], 1.0f);
        atomicAdd(&g_norm_dst[__ldg(&dst[e])], 1.0f);
    }
}

__global__ void k_norm() {
    int n = blockIdx.x * blockDim.x + threadIdx.x;
    if (n < NN) {
        g_norm_src[n] = rsqrtf(fmaxf(g_norm_src[n], 1.0f));
        g_norm_dst[n] = rsqrtf(fmaxf(g_norm_dst[n], 1.0f));
    }
}

// ---------------- layer-1 sparse scatter (one-hot messages) -----------------
// h0[src] has <=4 nonzeros (the 4 feature indices, duplicates counted), each
// valued 1. Message = norm_src[src] at those indices.
__global__ void k_scatter1(const int* __restrict__ src, const int* __restrict__ dst,
                           const int* __restrict__ feat) {
    int e = blockIdx.x * blockDim.x + threadIdx.x;
    if (e < EE) {
        int s = __ldg(&src[e]), d = __ldg(&dst[e]);
        float ns = g_norm_src[s];
        float* ag = &g_agg1[d * FL];
        int4 f = *(const int4*)&feat[s * 4];
        atomicAdd(&ag[f.x], ns);
        atomicAdd(&ag[f.y], ns);
        atomicAdd(&ag[f.z], ns);
        atomicAdd(&ag[f.w], ns);
    }
}

// ---------------- layer-2 dense scatter: agg2[dst] += h1[src]*norm_src[src] -
// 64 threads per edge, float4 load, 4 scalar atomics (compile to RED, no ret).
__global__ void k_scatter2(const int* __restrict__ src, const int* __restrict__ dst) {
    int t = blockIdx.x * blockDim.x + threadIdx.x;
    int e = t >> 6;
    int lane = t & 63;
    if (e < EE) {
        int s = __ldg(&src[e]), d = __ldg(&dst[e]);
        float ns = g_norm_src[s];
        float4 v = *(const float4*)&g_h1[s * DD + lane * 4];
        float* ag = &g_agg2[d * DD + lane * 4];
        atomicAdd(ag + 0, v.x * ns);
        atomicAdd(ag + 1, v.y * ns);
        atomicAdd(ag + 2, v.z * ns);
        atomicAdd(ag + 3, v.w * ns);
    }
}

// ---------------- fp32 GEMM: out[M,256] = (A[M,K]*rowscale) @ W[K,256] + b --
// 128x128 block tile, BK=16, 8x8 microtile, 256 threads. M%128==0, K%16==0.
__global__ __launch_bounds__(256) void k_gemm(
    const float* __restrict__ A, const float* __restrict__ rowscale,
    const float* __restrict__ W, const float* __restrict__ bias,
    float* __restrict__ out, int M, int K, int relu)
{
    const int NC = 256;
    __shared__ float As[16][128];
    __shared__ float Bs[16][128];
    int tid = threadIdx.x;
    int bm = blockIdx.x * 128;
    int bn = blockIdx.y * 128;
    int tx = tid & 15;
    int ty = tid >> 4;

    float acc[8][8];
#pragma unroll
    for (int i = 0; i < 8; i++)
#pragma unroll
        for (int j = 0; j < 8; j++) acc[i][j] = 0.f;

    for (int kt = 0; kt < K; kt += 16) {
        // A tile: 128 rows x 16 cols = 512 float4 slots
#pragma unroll
        for (int l = 0; l < 2; l++) {
            int slot = tid + l * 256;
            int row = slot >> 2;
            int c4 = slot & 3;
            float4 v = *(const float4*)&A[(size_t)(bm + row) * K + kt + c4 * 4];
            float sc = rowscale ? rowscale[bm + row] : 1.0f;
            As[c4 * 4 + 0][row] = v.x * sc;
            As[c4 * 4 + 1][row] = v.y * sc;
            As[c4 * 4 + 2][row] = v.z * sc;
            As[c4 * 4 + 3][row] = v.w * sc;
        }
        // B tile: 16 rows x 128 cols = 512 float4 slots
#pragma unroll
        for (int l = 0; l < 2; l++) {
            int slot = tid + l * 256;
            int kr = slot >> 5;
            int c4 = slot & 31;
            float4 v = *(const float4*)&W[(size_t)(kt + kr) * NC + bn + c4 * 4];
            *(float4*)&Bs[kr][c4 * 4] = v;
        }
        __syncthreads();
#pragma unroll
        for (int kk = 0; kk < 16; kk++) {
            float a[8], b[8];
            *(float4*)&a[0] = *(const float4*)&As[kk][ty * 8];
            *(float4*)&a[4] = *(const float4*)&As[kk][ty * 8 + 4];
            *(float4*)&b[0] = *(const float4*)&Bs[kk][tx * 8];
            *(float4*)&b[4] = *(const float4*)&Bs[kk][tx * 8 + 4];
#pragma unroll
            for (int i = 0; i < 8; i++)
#pragma unroll
                for (int j = 0; j < 8; j++)
                    acc[i][j] += a[i] * b[j];
        }
        __syncthreads();
    }

#pragma unroll
    for (int i = 0; i < 8; i++) {
        int row = bm + ty * 8 + i;
#pragma unroll
        for (int j = 0; j < 8; j += 4) {
            float4 v;
            v.x = acc[i][j + 0] + bias[bn + tx * 8 + j + 0];
            v.y = acc[i][j + 1] + bias[bn + tx * 8 + j + 1];
            v.z = acc[i][j + 2] + bias[bn + tx * 8 + j + 2];
            v.w = acc[i][j + 3] + bias[bn + tx * 8 + j + 3];
            if (relu) {
                v.x = fmaxf(v.x, 0.f); v.y = fmaxf(v.y, 0.f);
                v.z = fmaxf(v.z, 0.f); v.w = fmaxf(v.w, 0.f);
            }
            *(float4*)&out[(size_t)row * NC + bn + tx * 8 + j] = v;
        }
    }
}

// ---------------- mean row-norm of h2 ---------------------------------------
__global__ void k_normreduce() {
    int gwarp = (blockIdx.x * blockDim.x + threadIdx.x) >> 5;
    int lane = threadIdx.x & 31;
    float nrm = 0.f;
    {
        const float* row = &g_h2[(size_t)gwarp * DD];
        float ss = 0.f;
#pragma unroll
        for (int i = 0; i < 8; i++) {
            float v = row[lane + i * 32];
            ss += v * v;
        }
#pragma unroll
        for (int o = 16; o > 0; o >>= 1) ss += __shfl_down_sync(0xffffffffu, ss, o);
        nrm = sqrtf(ss);
    }
    __shared__ float wsum[8];
    if (lane == 0) wsum[threadIdx.x >> 5] = nrm;
    __syncthreads();
    if (threadIdx.x < 8) {
        float v = wsum[threadIdx.x];
#pragma unroll
        for (int o = 4; o > 0; o >>= 1) v += __shfl_down_sync(0xffu, v, o);
        if (threadIdx.x == 0) atomicAdd(&g_normsum, v);
    }
}

// ---------------- scale + segment pool (graph_ids is repeat(arange(B),30)) --
__global__ void k_pool(float* __restrict__ out) {
    int b = blockIdx.x, g = threadIdx.x;
    float factor = 16.0f * (float)NN / g_normsum;   // sqrt(256)/mean(norm)
    const float* base = &g_h2[(size_t)b * NATOMS * DD + g];
    float s = 0.f;
#pragma unroll
    for (int a = 0; a < NATOMS; a++) s += base[a * DD];
    s *= factor;
    out[b * 512 + g] = s;                // mol_embedding[:, :256]
    out[BB * 512 + b * DD + g] = s;      // mol_atom_embedding
}

// ---------------- reaction: item/target embeddings --------------------------
__global__ void k_molemb(const int* __restrict__ idl, const int* __restrict__ idt,
                         const float* __restrict__ mfea, const float* __restrict__ femb)
{
    int b = blockIdx.x, g = threadIdx.x;
    __shared__ float sm[4][40];
    __shared__ int ids[4];
    if (g < 4) ids[g] = (g < 2) ? idl[g * BB + b] : idt[(g - 2) * BB + b];
    __syncthreads();
    if (g < 160) sm[g / 40][g % 40] = mfea[(size_t)ids[g / 40] * 40 + (g % 40)];
    __syncthreads();
    float e0 = 0, e1 = 0, e2 = 0, e3 = 0;
#pragma unroll
    for (int j = 0; j < 40; j++) {
        float f = femb[j * DD + g];
        e0 += sm[0][j] * f;
        e1 += sm[1][j] * f;
        e2 += sm[2][j] * f;
        e3 += sm[3][j] * f;
    }
    g_item[(0 * BB + b) * DD + g] = e0;
    g_item[(1 * BB + b) * DD + g] = e1;
    g_target[b * DD + g] = 0.5f * (e0 + e1) + 0.5f * (e2 + e3);
}

// ---------------- fused neighbor attention per (s,b) ------------------------
__global__ __launch_bounds__(256) void k_att(
    const int* __restrict__ id_list, const int* __restrict__ neimat,
    const float* __restrict__ mfea, const float* __restrict__ femb,
    const float* __restrict__ attw)
{
    int sb = blockIdx.x;
    int s = sb >> 11;        // / 2048
    int b = sb & 2047;
    int g = threadIdx.x;

    __shared__ float nei[KNEI * DD];     // 32 KB
    __shared__ float mrow[KNEI * 40];    // 5 KB
    __shared__ float wv[DD];
    __shared__ float att[KNEI];
    __shared__ int nids[KNEI];

    int id = id_list[s * BB + b];
    if (g < KNEI) nids[g] = neimat[id * KNEI + g];
    __syncthreads();
    for (int i = g; i < KNEI * 40; i += 256)
        mrow[i] = mfea[(size_t)nids[i / 40] * 40 + (i % 40)];
    float itemv = g_item[(s * BB + b) * DD + g];
    wv[g] = itemv * g_target[b * DD + g] * attw[g];
    __syncthreads();

    // neighbor embeddings: nei[k][g] = sum_j mfea_row[k][j] * femb[j][g]
    for (int k = 0; k < KNEI; k++) {
        float acc = 0.f;
#pragma unroll
        for (int j = 0; j < 40; j++) acc += mrow[k * 40 + j] * femb[j * DD + g];
        nei[k * DD + g] = acc;
    }
    __syncthreads();

    // logits[k] = sum_g wv[g]*nei[k][g]  (att_b cancels in softmax)
    int warp = g >> 5, lane = g & 31;
#pragma unroll
    for (int kk = 0; kk < 4; kk++) {
        int k = warp * 4 + kk;
        float p = 0.f;
#pragma unroll
        for (int i = 0; i < 8; i++) p += wv[lane + i * 32] * nei[k * DD + lane + i * 32];
#pragma unroll
        for (int o = 16; o > 0; o >>= 1) p += __shfl_down_sync(0xffffffffu, p, o);
        if (lane == 0) att[k] = p;
    }
    __syncthreads();

    // softmax over 32 neighbors (warp 0)
    if (g < 32) {
        float x = att[g];
        float m = x;
#pragma unroll
        for (int o = 16; o > 0; o >>= 1) m = fmaxf(m, __shfl_xor_sync(0xffffffffu, m, o));
        float ex = expf(x - m);
        float su = ex;
#pragma unroll
        for (int o = 16; o > 0; o >>= 1) su += __shfl_xor_sync(0xffffffffu, su, o);
        att[g] = ex / su;
    }
    __syncthreads();

    float agg = 0.f;
#pragma unroll
    for (int k = 0; k < KNEI; k++) agg += att[k] * nei[k * DD + g];
    // mean over S=2 of (item + nei_agg)
    atomicAdd(&g_react[b * DD + g], 0.5f * (itemv + agg));
}

// ---------------- copy reaction embedding into mol_embedding[:,256:] --------
__global__ void k_copyreact(float* __restrict__ out) {
    int b = blockIdx.x, g = threadIdx.x;
    out[b * 512 + 256 + g] = g_react[b * DD + g];
}

// ---------------- launch ----------------------------------------------------
extern "C" void kernel_launch(void* const* d_in, const int* in_sizes, int n_in,
                              void* d_out, int out_size)
{
    const int*   node_feat = (const int*)d_in[0];
    const int*   edge_src  = (const int*)d_in[1];
    const int*   edge_dst  = (const int*)d_in[2];
    /* d_in[3] graph_ids: contiguous repeat(arange(B),30) -> implicit */
    const int*   id_list   = (const int*)d_in[4];
    const int*   id_tgt    = (const int*)d_in[5];
    const float* mfea      = (const float*)d_in[6];
    const int*   neimat    = (const int*)d_in[7];
    const float* W0        = (const float*)d_in[8];
    const float* b0        = (const float*)d_in[9];
    const float* W1        = (const float*)d_in[10];
    const float* b1        = (const float*)d_in[11];
    const float* femb      = (const float*)d_in[12];
    const float* attw      = (const float*)d_in[13];
    /* d_in[14] att_b: constant across K -> cancels in softmax */
    const float* cw        = (const float*)d_in[15];
    const float* cb        = (const float*)d_in[16];
    float* out = (float*)d_out;

    float *p_agg1, *p_agg2, *p_h1, *p_h2, *p_ndst, *p_react;
    cudaGetSymbolAddress((void**)&p_agg1,  g_agg1);
    cudaGetSymbolAddress((void**)&p_agg2,  g_agg2);
    cudaGetSymbolAddress((void**)&p_h1,    g_h1);
    cudaGetSymbolAddress((void**)&p_h2,    g_h2);
    cudaGetSymbolAddress((void**)&p_ndst,  g_norm_dst);
    cudaGetSymbolAddress((void**)&p_react, g_react);

    k_zero_all<<<NN * DD / 4 / 256, 256>>>();
    k_deg<<<EE / 256, 256>>>(edge_src, edge_dst);
    k_norm<<<NN / 256, 256>>>();

    // --- atom GCN chain ---
    k_scatter1<<<EE / 256, 256>>>(edge_src, edge_dst, node_feat);
    {
        dim3 grid(NN / 128, 2);
        k_gemm<<<grid, 256>>>(p_agg1, p_ndst, W0, b0, p_h1, NN, FL, 1);
    }
    k_scatter2<<<EE * 64 / 256, 256>>>(edge_src, edge_dst);
    {
        dim3 grid(NN / 128, 2);
        k_gemm<<<grid, 256>>>(p_agg2, p_ndst, W1, b1, p_h2, NN, DD, 0);
    }
    k_normreduce<<<NN * 32 / 256, 256>>>();
    k_pool<<<BB, 256>>>(out);

    // --- reaction / KG chain ---
    k_molemb<<<BB, 256>>>(id_list, id_tgt, mfea, femb);
    k_att<<<SSIDE * BB, 256>>>(id_list, neimat, mfea, femb, attw);
    k_copyreact<<<BB, 256>>>(out);
    {
        dim3 grid(BB / 128, 2);
        k_gemm<<<grid, 256>>>(p_react, nullptr, cw, cb,
                              out + BB * 512 + BB * DD, BB, DD, 0);
    }
}

// round 8
// speedup vs baseline: 1.3569x; 1.3569x over previous
#include <cuda_runtime.h>
#include <cuda_bf16.h>
#include <cstdint>

#define NN      61440        // nodes = 2048*30
#define EE      245760       // edges = 4*NN
#define BB      2048         // graphs
#define NATOMS  30
#define FL      64           // FEATURE_LEN
#define DD      256          // DIM_ATOM == DIM_GRAPH
#define SSIDE   2            // S
#define KNEI    32

// ---------------- device scratch (no runtime allocation allowed) ------------
__device__ float g_norm_src[NN];
__device__ float g_norm_dst[NN];
__device__ float g_agg1[NN * FL];
__device__ float g_h1[NN * DD];
__device__ float g_agg2[NN * DD];
__device__ float g_h2[NN * DD];
__device__ float g_item[SSIDE * BB * DD];
__device__ float g_target[BB * DD];
__device__ float g_react[BB * DD];
__device__ float g_normsum;

// ---------------- zero accumulators -----------------------------------------
__global__ void k_zero_all() {
    int t = blockIdx.x * blockDim.x + threadIdx.x;   // 15360*256 = 3,932,160
    float4 z = make_float4(0.f, 0.f, 0.f, 0.f);
    ((float4*)g_agg2)[t] = z;                         // NN*DD/4 exactly
    if (t < NN * FL / 4) ((float4*)g_agg1)[t] = z;
    if (t < NN / 4) {
        ((float4*)g_norm_src)[t] = z;
        ((float4*)g_norm_dst)[t] = z;
    }
    if (t < BB * DD / 4) ((float4*)g_react)[t] = z;
    if (t == 0) g_normsum = 0.f;
}

// ---------------- degrees + symmetric norm ----------------------------------
__global__ void k_deg(const int* __restrict__ src, const int* __restrict__ dst) {
    int e = blockIdx.x * blockDim.x + threadIdx.x;
    if (e < EE) {
        atomicAdd(&g_norm_src[__ldg(&src[e])], 1.0f);
        atomicAdd(&g_norm_dst[__ldg(&dst[e])], 1.0f);
    }
}

__global__ void k_norm() {
    int n = blockIdx.x * blockDim.x + threadIdx.x;
    if (n < NN) {
        g_norm_src[n] = rsqrtf(fmaxf(g_norm_src[n], 1.0f));
        g_norm_dst[n] = rsqrtf(fmaxf(g_norm_dst[n], 1.0f));
    }
}

// ---------------- layer-1 sparse scatter (one-hot messages) -----------------
__global__ void k_scatter1(const int* __restrict__ src, const int* __restrict__ dst,
                           const int* __restrict__ feat) {
    int e = blockIdx.x * blockDim.x + threadIdx.x;
    if (e < EE) {
        int s = __ldg(&src[e]), d = __ldg(&dst[e]);
        float ns = g_norm_src[s];
        float* ag = &g_agg1[d * FL];
        int4 f = *(const int4*)&feat[s * 4];
        atomicAdd(&ag[f.x], ns);
        atomicAdd(&ag[f.y], ns);
        atomicAdd(&ag[f.z], ns);
        atomicAdd(&ag[f.w], ns);
    }
}

// ---------------- layer-2 dense scatter: agg2[dst] += h1[src]*norm_src[src] -
// 64 threads/edge, one 128-bit vector atomic each (sm_90+ float4 atomicAdd).
__global__ void k_scatter2(const int* __restrict__ src, const int* __restrict__ dst) {
    int t = blockIdx.x * blockDim.x + threadIdx.x;
    int e = t >> 6;
    int lane = t & 63;
    if (e < EE) {
        int s = __ldg(&src[e]), d = __ldg(&dst[e]);
        float ns = g_norm_src[s];
        float4 v = *(const float4*)&g_h1[s * DD + lane * 4];
        v.x *= ns; v.y *= ns; v.z *= ns; v.w *= ns;
        atomicAdd((float4*)&g_agg2[d * DD + lane * 4], v);
    }
}

// ============================================================================
//  mma.sync bf16 3-split GEMM:  out[M,256] = (A*rowscale)[M,K] @ W[K,256] + b
//  Block tile 128x128 (grid.y = 2 covers N=256), 8 warps at 64x32 warp tiles.
//  K chunks of 32. A,B split x = hi(bf16) + lo(bf16); D = AhBh + AlBh + AhBl.
// ============================================================================
#define SMS 36   // smem row stride in bf16 elements (32 + 4 pad)

__device__ __forceinline__ void mma16816(float* c, const uint32_t* a,
                                         const uint32_t* b) {
    asm volatile(
        "mma.sync.aligned.m16n8k16.row.col.f32.bf16.bf16.f32 "
        "{%0,%1,%2,%3}, {%4,%5,%6,%7}, {%8,%9}, {%0,%1,%2,%3};"
        : "+f"(c[0]), "+f"(c[1]), "+f"(c[2]), "+f"(c[3])
        : "r"(a[0]), "r"(a[1]), "r"(a[2]), "r"(a[3]), "r"(b[0]), "r"(b[1]));
}

__global__ __launch_bounds__(256) void k_mgemm(
    const float* __restrict__ A, const float* __restrict__ rowscale,
    const float* __restrict__ W, const float* __restrict__ bias,
    float* __restrict__ out, int K, int relu)
{
    __shared__ __nv_bfloat16 AsH[128 * SMS];
    __shared__ __nv_bfloat16 AsL[128 * SMS];
    __shared__ __nv_bfloat16 BsH[128 * SMS];
    __shared__ __nv_bfloat16 BsL[128 * SMS];

    int tid = threadIdx.x;
    int wid = tid >> 5, lane = tid & 31;
    int warpM = wid & 1, warpN = wid >> 1;     // 2 x 4 warp grid
    int g = lane >> 2, tg = lane & 3;          // mma group / thread-in-group
    int bm = blockIdx.x * 128;
    int bn = blockIdx.y * 128;

    float acc[4][4][4];
#pragma unroll
    for (int mi = 0; mi < 4; mi++)
#pragma unroll
        for (int ni = 0; ni < 4; ni++)
#pragma unroll
            for (int r = 0; r < 4; r++) acc[mi][ni][r] = 0.f;

    int arow = tid >> 1, ahalf = tid & 1;      // A loader: 128 rows x 2 halves
    float rsc = rowscale ? __ldg(&rowscale[bm + arow]) : 1.0f;
    int bk = tid >> 3, bn16 = (tid & 7) * 16;  // B loader: 32 k-rows x 8 n-grp

    for (int kc = 0; kc < K; kc += 32) {
        // ---- A chunk 128x32: split hi/lo ----
        {
            const float* ap = &A[(size_t)(bm + arow) * K + kc + ahalf * 16];
            int base = arow * SMS + ahalf * 16;
#pragma unroll
            for (int i = 0; i < 4; i++) {
                float4 v = *(const float4*)(ap + i * 4);
                v.x *= rsc; v.y *= rsc; v.z *= rsc; v.w *= rsc;
                __nv_bfloat16 hx = __float2bfloat16_rn(v.x);
                __nv_bfloat16 hy = __float2bfloat16_rn(v.y);
                __nv_bfloat16 hz = __float2bfloat16_rn(v.z);
                __nv_bfloat16 hw = __float2bfloat16_rn(v.w);
                __nv_bfloat162 hxy = __halves2bfloat162(hx, hy);
                __nv_bfloat162 hzw = __halves2bfloat162(hz, hw);
                __nv_bfloat162 lxy = __floats2bfloat162_rn(
                    v.x - __bfloat162float(hx), v.y - __bfloat162float(hy));
                __nv_bfloat162 lzw = __floats2bfloat162_rn(
                    v.z - __bfloat162float(hz), v.w - __bfloat162float(hw));
                *(__nv_bfloat162*)&AsH[base + i * 4]     = hxy;
                *(__nv_bfloat162*)&AsH[base + i * 4 + 2] = hzw;
                *(__nv_bfloat162*)&AsL[base + i * 4]     = lxy;
                *(__nv_bfloat162*)&AsL[base + i * 4 + 2] = lzw;
            }
        }
        // ---- B chunk 32x128 -> transposed Bs[n][k], split hi/lo ----
        {
            const float* wp = &W[(size_t)(kc + bk) * 256 + bn + bn16];
#pragma unroll
            for (int j4 = 0; j4 < 4; j4++) {
                float4 v = *(const float4*)(wp + j4 * 4);
                float vv[4] = {v.x, v.y, v.z, v.w};
#pragma unroll
                for (int e2 = 0; e2 < 4; e2++) {
                    int n = bn16 + j4 * 4 + e2;
                    __nv_bfloat16 h = __float2bfloat16_rn(vv[e2]);
                    BsH[n * SMS + bk] = h;
                    BsL[n * SMS + bk] = __float2bfloat16_rn(vv[e2] - __bfloat162float(h));
                }
            }
        }
        __syncthreads();

#pragma unroll
        for (int ks = 0; ks < 32; ks += 16) {
            uint32_t aH[4][4], aL[4][4], bH[4][2], bL[4][2];
#pragma unroll
            for (int mi = 0; mi < 4; mi++) {
                int r0 = (warpM * 64 + mi * 16 + g) * SMS + ks + tg * 2;
                int r1 = r0 + 8 * SMS;
                aH[mi][0] = *(const uint32_t*)&AsH[r0];
                aH[mi][1] = *(const uint32_t*)&AsH[r1];
                aH[mi][2] = *(const uint32_t*)&AsH[r0 + 8];
                aH[mi][3] = *(const uint32_t*)&AsH[r1 + 8];
                aL[mi][0] = *(const uint32_t*)&AsL[r0];
                aL[mi][1] = *(const uint32_t*)&AsL[r1];
                aL[mi][2] = *(const uint32_t*)&AsL[r0 + 8];
                aL[mi][3] = *(const uint32_t*)&AsL[r1 + 8];
            }
#pragma unroll
            for (int ni = 0; ni < 4; ni++) {
                int n0 = (warpN * 32 + ni * 8 + g) * SMS + ks + tg * 2;
                bH[ni][0] = *(const uint32_t*)&BsH[n0];
                bH[ni][1] = *(const uint32_t*)&BsH[n0 + 8];
                bL[ni][0] = *(const uint32_t*)&BsL[n0];
                bL[ni][1] = *(const uint32_t*)&BsL[n0 + 8];
            }
#pragma unroll
            for (int mi = 0; mi < 4; mi++)
#pragma unroll
                for (int ni = 0; ni < 4; ni++) {
                    mma16816(acc[mi][ni], aH[mi], bH[ni]);
                    mma16816(acc[mi][ni], aL[mi], bH[ni]);
                    mma16816(acc[mi][ni], aH[mi], bL[ni]);
                }
        }
        __syncthreads();
    }

    // ---- epilogue: bias (+relu), write fp32 ----
#pragma unroll
    for (int mi = 0; mi < 4; mi++) {
        int row0 = bm + warpM * 64 + mi * 16 + g;
#pragma unroll
        for (int ni = 0; ni < 4; ni++) {
            int col = bn + warpN * 32 + ni * 8 + tg * 2;
            float b0 = __ldg(&bias[col]), b1 = __ldg(&bias[col + 1]);
            float2 v0, v1;
            v0.x = acc[mi][ni][0] + b0; v0.y = acc[mi][ni][1] + b1;
            v1.x = acc[mi][ni][2] + b0; v1.y = acc[mi][ni][3] + b1;
            if (relu) {
                v0.x = fmaxf(v0.x, 0.f); v0.y = fmaxf(v0.y, 0.f);
                v1.x = fmaxf(v1.x, 0.f); v1.y = fmaxf(v1.y, 0.f);
            }
            *(float2*)&out[(size_t)row0 * 256 + col] = v0;
            *(float2*)&out[(size_t)(row0 + 8) * 256 + col] = v1;
        }
    }
}

// ---------------- mean row-norm of h2 ---------------------------------------
__global__ void k_normreduce() {
    int gwarp = (blockIdx.x * blockDim.x + threadIdx.x) >> 5;
    int lane = threadIdx.x & 31;
    float nrm = 0.f;
    {
        const float* row = &g_h2[(size_t)gwarp * DD];
        float ss = 0.f;
#pragma unroll
        for (int i = 0; i < 8; i++) {
            float v = row[lane + i * 32];
            ss += v * v;
        }
#pragma unroll
        for (int o = 16; o > 0; o >>= 1) ss += __shfl_down_sync(0xffffffffu, ss, o);
        nrm = sqrtf(ss);
    }
    __shared__ float wsum[8];
    if (lane == 0) wsum[threadIdx.x >> 5] = nrm;
    __syncthreads();
    if (threadIdx.x < 8) {
        float v = wsum[threadIdx.x];
#pragma unroll
        for (int o = 4; o > 0; o >>= 1) v += __shfl_down_sync(0xffu, v, o);
        if (threadIdx.x == 0) atomicAdd(&g_normsum, v);
    }
}

// ---------------- scale + segment pool --------------------------------------
__global__ void k_pool(float* __restrict__ out) {
    int b = blockIdx.x, g = threadIdx.x;
    float factor = 16.0f * (float)NN / g_normsum;   // sqrt(256)/mean(norm)
    const float* base = &g_h2[(size_t)b * NATOMS * DD + g];
    float s = 0.f;
#pragma unroll
    for (int a = 0; a < NATOMS; a++) s += base[a * DD];
    s *= factor;
    out[b * 512 + g] = s;                // mol_embedding[:, :256]
    out[BB * 512 + b * DD + g] = s;      // mol_atom_embedding
}

// ---------------- reaction: item/target embeddings --------------------------
__global__ void k_molemb(const int* __restrict__ idl, const int* __restrict__ idt,
                         const float* __restrict__ mfea, const float* __restrict__ femb)
{
    int b = blockIdx.x, g = threadIdx.x;
    __shared__ float sm[4][40];
    __shared__ int ids[4];
    if (g < 4) ids[g] = (g < 2) ? idl[g * BB + b] : idt[(g - 2) * BB + b];
    __syncthreads();
    if (g < 160) sm[g / 40][g % 40] = mfea[(size_t)ids[g / 40] * 40 + (g % 40)];
    __syncthreads();
    float e0 = 0, e1 = 0, e2 = 0, e3 = 0;
#pragma unroll
    for (int j = 0; j < 40; j++) {
        float f = femb[j * DD + g];
        e0 += sm[0][j] * f;
        e1 += sm[1][j] * f;
        e2 += sm[2][j] * f;
        e3 += sm[3][j] * f;
    }
    g_item[(0 * BB + b) * DD + g] = e0;
    g_item[(1 * BB + b) * DD + g] = e1;
    g_target[b * DD + g] = 0.5f * (e0 + e1) + 0.5f * (e2 + e3);
}

// ---------------- fused neighbor attention per (s,b) ------------------------
__global__ __launch_bounds__(256) void k_att(
    const int* __restrict__ id_list, const int* __restrict__ neimat,
    const float* __restrict__ mfea, const float* __restrict__ femb,
    const float* __restrict__ attw)
{
    int sb = blockIdx.x;
    int s = sb >> 11;        // / 2048
    int b = sb & 2047;
    int g = threadIdx.x;

    __shared__ float nei[KNEI * DD];     // 32 KB
    __shared__ float mrow[KNEI * 40];    // 5 KB
    __shared__ float wv[DD];
    __shared__ float att[KNEI];
    __shared__ int nids[KNEI];

    int id = id_list[s * BB + b];
    if (g < KNEI) nids[g] = neimat[id * KNEI + g];
    __syncthreads();
    for (int i = g; i < KNEI * 40; i += 256)
        mrow[i] = mfea[(size_t)nids[i / 40] * 40 + (i % 40)];
    float itemv = g_item[(s * BB + b) * DD + g];
    wv[g] = itemv * g_target[b * DD + g] * attw[g];
    __syncthreads();

    for (int k = 0; k < KNEI; k++) {
        float acc = 0.f;
#pragma unroll
        for (int j = 0; j < 40; j++) acc += mrow[k * 40 + j] * femb[j * DD + g];
        nei[k * DD + g] = acc;
    }
    __syncthreads();

    int warp = g >> 5, lane = g & 31;
#pragma unroll
    for (int kk = 0; kk < 4; kk++) {
        int k = warp * 4 + kk;
        float p = 0.f;
#pragma unroll
        for (int i = 0; i < 8; i++) p += wv[lane + i * 32] * nei[k * DD + lane + i * 32];
#pragma unroll
        for (int o = 16; o > 0; o >>= 1) p += __shfl_down_sync(0xffffffffu, p, o);
        if (lane == 0) att[k] = p;
    }
    __syncthreads();

    if (g < 32) {
        float x = att[g];
        float m = x;
#pragma unroll
        for (int o = 16; o > 0; o >>= 1) m = fmaxf(m, __shfl_xor_sync(0xffffffffu, m, o));
        float ex = expf(x - m);
        float su = ex;
#pragma unroll
        for (int o = 16; o > 0; o >>= 1) su += __shfl_xor_sync(0xffffffffu, su, o);
        att[g] = ex / su;
    }
    __syncthreads();

    float agg = 0.f;
#pragma unroll
    for (int k = 0; k < KNEI; k++) agg += att[k] * nei[k * DD + g];
    atomicAdd(&g_react[b * DD + g], 0.5f * (itemv + agg));
}

// ---------------- copy reaction embedding into mol_embedding[:,256:] --------
__global__ void k_copyreact(float* __restrict__ out) {
    int b = blockIdx.x, g = threadIdx.x;
    out[b * 512 + 256 + g] = g_react[b * DD + g];
}

// ---------------- launch ----------------------------------------------------
extern "C" void kernel_launch(void* const* d_in, const int* in_sizes, int n_in,
                              void* d_out, int out_size)
{
    const int*   node_feat = (const int*)d_in[0];
    const int*   edge_src  = (const int*)d_in[1];
    const int*   edge_dst  = (const int*)d_in[2];
    /* d_in[3] graph_ids: contiguous repeat(arange(B),30) -> implicit */
    const int*   id_list   = (const int*)d_in[4];
    const int*   id_tgt    = (const int*)d_in[5];
    const float* mfea      = (const float*)d_in[6];
    const int*   neimat    = (const int*)d_in[7];
    const float* W0        = (const float*)d_in[8];
    const float* b0        = (const float*)d_in[9];
    const float* W1        = (const float*)d_in[10];
    const float* b1        = (const float*)d_in[11];
    const float* femb      = (const float*)d_in[12];
    const float* attw      = (const float*)d_in[13];
    /* d_in[14] att_b cancels in softmax */
    const float* cw        = (const float*)d_in[15];
    const float* cb        = (const float*)d_in[16];
    float* out = (float*)d_out;

    float *p_agg1, *p_agg2, *p_react, *p_ndst;
    float *p_h1, *p_h2;
    cudaGetSymbolAddress((void**)&p_agg1,  g_agg1);
    cudaGetSymbolAddress((void**)&p_agg2,  g_agg2);
    cudaGetSymbolAddress((void**)&p_h1,    g_h1);
    cudaGetSymbolAddress((void**)&p_h2,    g_h2);
    cudaGetSymbolAddress((void**)&p_ndst,  g_norm_dst);
    cudaGetSymbolAddress((void**)&p_react, g_react);

    k_zero_all<<<NN * DD / 4 / 256, 256>>>();
    k_deg<<<EE / 256, 256>>>(edge_src, edge_dst);
    k_norm<<<NN / 256, 256>>>();

    // --- atom GCN chain ---
    k_scatter1<<<EE / 256, 256>>>(edge_src, edge_dst, node_feat);
    {
        dim3 grid(NN / 128, 2);
        k_mgemm<<<grid, 256>>>(p_agg1, p_ndst, W0, b0, p_h1, FL, 1);
    }
    k_scatter2<<<EE * 64 / 256, 256>>>(edge_src, edge_dst);
    {
        dim3 grid(NN / 128, 2);
        k_mgemm<<<grid, 256>>>(p_agg2, p_ndst, W1, b1, p_h2, DD, 0);
    }
    k_normreduce<<<NN * 32 / 256, 256>>>();
    k_pool<<<BB, 256>>>(out);

    // --- reaction / KG chain ---
    k_molemb<<<BB, 256>>>(id_list, id_tgt, mfea, femb);
    k_att<<<SSIDE * BB, 256>>>(id_list, neimat, mfea, femb, attw);
    k_copyreact<<<BB, 256>>>(out);
    {
        dim3 grid(BB / 128, 2);
        k_mgemm<<<grid, 256>>>(p_react, nullptr, cw, cb,
                               out + BB * 512 + BB * DD, DD, 0);
    }
}